// round 9
// baseline (speedup 1.0000x reference)
#include <cuda_runtime.h>
#include <math.h>

// Problem dims
#define SEQLEN 8192
#define INSZ   512
#define HSZ    2048
#define OSZ    512

// Recurrence: 128 CTAs x 16 rows, 8 warps/CTA.
// Warp w owns k-slice [256w, 256w+256) for ALL 16 rows (h read once per CTA).
// Lane l: row r = l&15, parity odd = l>>4; handles float4 indices 2j+odd of
// the warp's 64-float4 slice -> the 2 distinct addresses per warp-LDG are
// 16B-adjacent (same 32B sector): zero overfetch.
#define NCTA 128
#define RPC  16

// Scratch (device globals: allocation-free rule)
__device__ float    g_A[(size_t)SEQLEN * HSZ];         // U x_t + U_b ; reused as Z
__device__ float    g_Hst[(size_t)(SEQLEN + 1) * HSZ]; // h_0 .. h_8192
__device__ unsigned g_ctr;                             // single release counter

// ---------------------------------------------------------------------------
// PTX helpers
// ---------------------------------------------------------------------------
static __device__ __forceinline__ unsigned ld_acq(const unsigned* p) {
    unsigned v;
    asm volatile("ld.acquire.gpu.global.u32 %0, [%1];" : "=r"(v) : "l"(p));
    return v;
}
static __device__ __forceinline__ void red_rel_add(unsigned* p, unsigned v) {
    asm volatile("red.release.gpu.global.add.u32 [%0], %1;" :: "l"(p), "r"(v));
}
// packed f32x2 FMA: acc.{lo,hi} += a*b  (Blackwell; 2x fp32 rate)
static __device__ __forceinline__ void fma2(unsigned long long& acc,
                                            float a0, float a1, float b0, float b1) {
    asm("{\n\t"
        ".reg .b64 ta, tb;\n\t"
        "mov.b64 ta, {%1, %2};\n\t"
        "mov.b64 tb, {%3, %4};\n\t"
        "fma.rn.f32x2 %0, ta, tb, %0;\n\t"
        "}"
        : "+l"(acc) : "f"(a0), "f"(a1), "f"(b0), "f"(b1));
}
static __device__ __forceinline__ float unpack_sum(unsigned long long acc) {
    float lo, hi;
    asm("mov.b64 {%0, %1}, %2;" : "=f"(lo), "=f"(hi) : "l"(acc));
    return lo + hi;
}
// tanh(x) = 1 - 2/(e^{2x}+1): MUFU ex2 + approx div (validated rel_err 1.1e-6)
static __device__ __forceinline__ float fast_tanh(float x) {
    float e = __expf(2.f * x);
    return 1.f - __fdividef(2.f, e + 1.f);
}

// ---------------------------------------------------------------------------
// Init: reset counter, load h_0
// ---------------------------------------------------------------------------
__global__ void init_k(const float* __restrict__ hidden) {
    int i = blockIdx.x * blockDim.x + threadIdx.x;
    if (i == 0) g_ctr = 0;
    if (i < HSZ) g_Hst[i] = hidden[i];
}

// ---------------------------------------------------------------------------
// SGEMM: C[M,N] = A[M,K] * B[N,K]^T + bias[N]   (row-major)
// ---------------------------------------------------------------------------
__global__ __launch_bounds__(256) void sgemm_tn_bias(
    const float* __restrict__ A, const float* __restrict__ B,
    const float* __restrict__ bias, float* __restrict__ C,
    int M, int N, int K)
{
    __shared__ float As[8][128];
    __shared__ float Bs[8][128];
    const int tid  = threadIdx.x;
    const int tx   = tid & 15;
    const int ty   = tid >> 4;
    const int lrow = tid >> 1;
    const int lcol = (tid & 1) * 4;

    const float* Ap = A + (size_t)(blockIdx.y * 128 + lrow) * K + lcol;
    const float* Bp = B + (size_t)(blockIdx.x * 128 + lrow) * K + lcol;

    float acc[8][8];
    #pragma unroll
    for (int i = 0; i < 8; ++i)
        #pragma unroll
        for (int j = 0; j < 8; ++j) acc[i][j] = 0.f;

    for (int k0 = 0; k0 < K; k0 += 8) {
        float4 a4 = *(const float4*)(Ap + k0);
        float4 b4 = *(const float4*)(Bp + k0);
        As[lcol + 0][lrow] = a4.x; As[lcol + 1][lrow] = a4.y;
        As[lcol + 2][lrow] = a4.z; As[lcol + 3][lrow] = a4.w;
        Bs[lcol + 0][lrow] = b4.x; Bs[lcol + 1][lrow] = b4.y;
        Bs[lcol + 2][lrow] = b4.z; Bs[lcol + 3][lrow] = b4.w;
        __syncthreads();
        #pragma unroll
        for (int k = 0; k < 8; ++k) {
            float ar[8], br[8];
            *(float4*)&ar[0] = *(const float4*)&As[k][ty * 8];
            *(float4*)&ar[4] = *(const float4*)&As[k][ty * 8 + 4];
            *(float4*)&br[0] = *(const float4*)&Bs[k][tx * 8];
            *(float4*)&br[4] = *(const float4*)&Bs[k][tx * 8 + 4];
            #pragma unroll
            for (int i = 0; i < 8; ++i)
                #pragma unroll
                for (int j = 0; j < 8; ++j)
                    acc[i][j] = fmaf(ar[i], br[j], acc[i][j]);
        }
        __syncthreads();
    }

    const int cm = blockIdx.y * 128 + ty * 8;
    const int cn = blockIdx.x * 128 + tx * 8;
    float bv[8];
    #pragma unroll
    for (int j = 0; j < 8; ++j) bv[j] = bias[cn + j];
    #pragma unroll
    for (int i = 0; i < 8; ++i) {
        float4 o0, o1;
        o0.x = acc[i][0] + bv[0]; o0.y = acc[i][1] + bv[1];
        o0.z = acc[i][2] + bv[2]; o0.w = acc[i][3] + bv[3];
        o1.x = acc[i][4] + bv[4]; o1.y = acc[i][5] + bv[5];
        o1.z = acc[i][6] + bv[6]; o1.w = acc[i][7] + bv[7];
        *(float4*)(C + (size_t)(cm + i) * N + cn)     = o0;
        *(float4*)(C + (size_t)(cm + i) * N + cn + 4) = o1;
    }
}

// ---------------------------------------------------------------------------
// Persistent recurrence, k-sliced: h_{i+1} = tanh(A[i] + W h_i + W_b)
// h is read ONCE per CTA per step (1MB/step chip-wide vs 8MB in R8).
// Lane (r, odd): dot(W[row][k-slice half], h[k-slice half]) serial in regs;
// row sum = one shfl_xor(16); cross-warp via padded SMEM + leader warp.
// Sync: measured-best single counter (tid0 poll + red.release.add).
// ---------------------------------------------------------------------------
__global__ __launch_bounds__(256, 1) void rnn_recur(
    const float* __restrict__ W, const float* __restrict__ Wb)
{
    const int tid  = threadIdx.x;
    const int cta  = blockIdx.x;
    const int warp = tid >> 5;        // 0..7  k-slice
    const int lane = tid & 31;
    const int r    = lane & 15;       // row within CTA
    const int odd  = lane >> 4;       // float4 parity within slice
    const int grow = cta * RPC + r;

    // W regs: float4 indices 2j+odd of W[grow][256*warp .. +256)
    float4 wreg[32];
    {
        const float4* Wg = (const float4*)(W + (size_t)grow * HSZ + 256 * warp);
        #pragma unroll
        for (int j = 0; j < 32; ++j) wreg[j] = Wg[2 * j + odd];
    }
    const float wb = (tid < RPC) ? Wb[cta * RPC + tid] : 0.f;

    __shared__ __align__(16) float part_s[8][17];   // [warp][row], pad 17
    __syncthreads();

    for (int i = 0; i < SEQLEN; ++i) {
        // Prefetch A[i] (flag-independent): hides DRAM under the wait
        float a_val = 0.f;
        if (tid < RPC) a_val = g_A[(size_t)i * HSZ + cta * RPC + tid];

        // Wait for all CTAs to have published h_i (single counter, tid0)
        if (i > 0) {
            if (tid == 0) {
                const unsigned target = (unsigned)i * NCTA;
                while (ld_acq(&g_ctr) < target) { }
            }
            __syncthreads();
        }

        // This lane's 128-MAC dot: h float4s 2j+odd of slice [256w, 256w+256)
        const float4* hp = (const float4*)(g_Hst + (size_t)i * HSZ + 256 * warp);
        unsigned long long acc0 = 0ull, acc1 = 0ull, acc2 = 0ull, acc3 = 0ull;
        #pragma unroll
        for (int c = 0; c < 4; ++c) {
            float4 hb[8];
            #pragma unroll
            for (int j = 0; j < 8; ++j) hb[j] = hp[2 * (c * 8 + j) + odd];
            #pragma unroll
            for (int j = 0; j < 8; ++j) {
                float4 w4 = wreg[c * 8 + j];
                if (j & 1) { fma2(acc2, hb[j].x, hb[j].y, w4.x, w4.y);
                             fma2(acc3, hb[j].z, hb[j].w, w4.z, w4.w); }
                else       { fma2(acc0, hb[j].x, hb[j].y, w4.x, w4.y);
                             fma2(acc1, hb[j].z, hb[j].w, w4.z, w4.w); }
            }
        }
        float p = (unpack_sum(acc0) + unpack_sum(acc1))
                + (unpack_sum(acc2) + unpack_sum(acc3));

        // Combine the two slice-halves of row r: one shfl
        p += __shfl_xor_sync(0xffffffffu, p, 16);
        if (odd == 0) part_s[warp][r] = p;       // 16 consecutive banks: clean
        __syncthreads();

        // Warp-0 leaders (tid<16): 8-way cross-warp add, tanh, store, release
        if (tid < RPC) {
            float s = 0.f;
            #pragma unroll
            for (int w = 0; w < 8; ++w) s += part_s[w][tid];  // stride-17: no conflict
            float hv = fast_tanh(s + a_val + wb);
            g_Hst[(size_t)(i + 1) * HSZ + cta * RPC + tid] = hv;
            __syncwarp(0x0000ffffu);             // order the 16 h stores
            if (tid == 0) red_rel_add(&g_ctr, 1u);
        }
        // Non-leader warps run ahead to the next post-poll barrier; they can
        // only rewrite part_s after that barrier releases, which requires
        // warp 0 (the reader) to have finished the leader phase. Race-free.
    }
}

// ---------------------------------------------------------------------------
// log_softmax over rows of Z [SEQLEN, OSZ], one warp per row
// ---------------------------------------------------------------------------
__global__ __launch_bounds__(128) void logsoftmax_k(
    const float* __restrict__ Z, float* __restrict__ Y)
{
    int warp = (blockIdx.x * blockDim.x + threadIdx.x) >> 5;
    int lane = threadIdx.x & 31;
    if (warp >= SEQLEN) return;
    const float* z = Z + (size_t)warp * OSZ;
    float v[16];
    float m = -INFINITY;
    #pragma unroll
    for (int j = 0; j < 16; ++j) {
        v[j] = z[lane + 32 * j];
        m = fmaxf(m, v[j]);
    }
    #pragma unroll
    for (int o = 16; o > 0; o >>= 1) m = fmaxf(m, __shfl_xor_sync(~0u, m, o));
    float s = 0.f;
    #pragma unroll
    for (int j = 0; j < 16; ++j) s += __expf(v[j] - m);
    #pragma unroll
    for (int o = 16; o > 0; o >>= 1) s += __shfl_xor_sync(~0u, s, o);
    float lse = m + __logf(s);
    float* y = Y + (size_t)warp * OSZ;
    #pragma unroll
    for (int j = 0; j < 16; ++j) y[lane + 32 * j] = v[j] - lse;
}

__global__ void copy_hfinal(float* __restrict__ out) {
    int i = blockIdx.x * blockDim.x + threadIdx.x;
    if (i < HSZ) out[i] = g_Hst[(size_t)SEQLEN * HSZ + i];
}

// ---------------------------------------------------------------------------
// kernel_launch
// Inputs: 0 input[8192,512] 1 hidden[1,2048] 2 U_w[2048,512] 3 U_b[2048]
//         4 W_w[2048,2048]  5 W_b[2048]      6 V_w[512,2048]  7 V_b[512]
// Output: y[8192,512] ++ h_final[2048]
// ---------------------------------------------------------------------------
extern "C" void kernel_launch(void* const* d_in, const int* in_sizes, int n_in,
                              void* d_out, int out_size)
{
    (void)in_sizes; (void)n_in; (void)out_size;
    const float* input  = (const float*)d_in[0];
    const float* hidden = (const float*)d_in[1];
    const float* U_w    = (const float*)d_in[2];
    const float* U_b    = (const float*)d_in[3];
    const float* W_w    = (const float*)d_in[4];
    const float* W_b    = (const float*)d_in[5];
    const float* V_w    = (const float*)d_in[6];
    const float* V_b    = (const float*)d_in[7];
    float* out = (float*)d_out;

    float *pA, *pH;
    cudaGetSymbolAddress((void**)&pA, g_A);
    cudaGetSymbolAddress((void**)&pH, g_Hst);

    // 1) reset counter + h_0
    init_k<<<8, 256>>>(hidden);

    // 2) A = X U^T + U_b : [8192,2048]
    sgemm_tn_bias<<<dim3(HSZ / 128, SEQLEN / 128), 256>>>(
        input, U_w, U_b, pA, SEQLEN, HSZ, INSZ);

    // 3) sequential recurrence -> g_Hst rows 1..8192
    rnn_recur<<<NCTA, 256>>>(W_w, W_b);

    // 4) Z = H V^T + V_b : [8192,512]  (reuse g_A as Z; H rows 1..8192)
    sgemm_tn_bias<<<dim3(OSZ / 128, SEQLEN / 128), 256>>>(
        pH + HSZ, V_w, V_b, pA, SEQLEN, OSZ, HSZ);

    // 5) y = log_softmax(Z) ; h_final
    logsoftmax_k<<<SEQLEN / 4, 128>>>(pA, out);
    copy_hfinal<<<8, 256>>>(out + (size_t)SEQLEN * OSZ);
}